// round 3
// baseline (speedup 1.0000x reference)
#include <cuda_runtime.h>
#include <cstdint>

namespace {
constexpr int kB       = 16384;
constexpr int kF       = 50;
constexpr int kE       = 64;
constexpr int kD       = 128;
constexpr int kFP      = 56;          // K padded to 7 * 8
constexpr int kK       = 7;           // k-steps of 8
constexpr int kTileW   = kFP * kE;    // 3584 words per X buffer
constexpr int kStages  = 4;
constexpr int kSlots   = 2;           // 2 b's in flight per iteration
constexpr int kThreads = 512;         // 16 warps: 8 warps per b
constexpr int kIters   = 8;           // b-pairs per CTA
constexpr int kGrid    = kB / (2 * kIters);               // 1024 CTAs
constexpr int kSmemBytes = kStages * kSlots * kTileW * 4; // 114688 B
}

__device__ __forceinline__ uint32_t f2tf32(float x) {
    uint32_t r;
    asm("cvt.rna.tf32.f32 %0, %1;" : "=r"(r) : "f"(x));
    return r;
}

__device__ __forceinline__ void mma8(float d[4], const uint32_t a[4],
                                     uint32_t b0, uint32_t b1) {
    asm volatile(
        "mma.sync.aligned.m16n8k8.row.col.f32.tf32.tf32.f32 "
        "{%0,%1,%2,%3}, {%4,%5,%6,%7}, {%8,%9}, {%0,%1,%2,%3};\n"
        : "+f"(d[0]), "+f"(d[1]), "+f"(d[2]), "+f"(d[3])
        : "r"(a[0]), "r"(a[1]), "r"(a[2]), "r"(a[3]), "r"(b0), "r"(b1));
}

__global__ void __launch_bounds__(kThreads, 1)
InnerProduct_tf32_kernel(const float* __restrict__ X,
                         const float* __restrict__ Th,
                         float* __restrict__ out) {
    extern __shared__ float sm[];
    const int tid  = threadIdx.x;
    const int lane = tid & 31;
    const int warp = tid >> 5;
    const int g    = lane >> 2;   // groupID (0..7)
    const int q    = lane & 3;    // threadID_in_group (0..3)
    const int slot = warp >> 3;   // which b of the pair (0/1)
    const int dbase = (warp & 7) << 4;  // 16 d-rows per warp

    // ---- Stage Theta into smem (zero-padded K: 50 -> 56) ----
    for (int i = tid; i < kD * kFP; i += kThreads) sm[i] = 0.f;
    __syncthreads();
    for (int i = tid; i < kD * kF; i += kThreads) {
        int d = i / kF;
        int f = i - d * kF;
        sm[d * kFP + f] = Th[i];
    }
    __syncthreads();

    // ---- Cache A fragments (Theta, 16 d-rows) in registers permanently ----
    // m16n8k8 tf32 A layout: a0:(g,q) a1:(g+8,q) a2:(g,q+4) a3:(g+8,q+4)
    uint32_t af[kK][4];
#pragma unroll
    for (int k = 0; k < kK; ++k) {
        const int r = dbase + g;
        const int c = 8 * k + q;
        af[k][0] = f2tf32(sm[r * kFP + c]);
        af[k][1] = f2tf32(sm[(r + 8) * kFP + c]);
        af[k][2] = f2tf32(sm[r * kFP + c + 4]);
        af[k][3] = f2tf32(sm[(r + 8) * kFP + c + 4]);
    }
    __syncthreads();

    // ---- Zero K-padding rows (f = 50..55) of all 8 X buffers (once).
    // cp.async only ever writes f < 50, and Theta pads are zero, so the
    // pad products are exactly 0; these just need to be finite.
#pragma unroll
    for (int buf = 0; buf < kStages * kSlots; ++buf)
        for (int i = tid; i < (kFP - kF) * kE; i += kThreads)
            sm[buf * kTileW + kF * kE + i] = 0.f;

    const uint32_t sbase = (uint32_t)__cvta_generic_to_shared(sm);
    const size_t bstart = (size_t)blockIdx.x * (2 * kIters);

    // X[b] tile is [F=50][E=64], e contiguous. Stored with XOR swizzle:
    // word(f,e) = f*64 + (e ^ ((f&7)<<3)); 16B blocks stay contiguous so
    // cp.async works, and both B-fragment LDS patterns are conflict-free.
    auto load_pair = [&](int j) {
        const int stage = j % kStages;
#pragma unroll
        for (int s2 = 0; s2 < kSlots; ++s2) {
            const float* src = X + (bstart + 2 * j + s2) * (size_t)(kF * kE);
            const uint32_t dbuf =
                sbase + (uint32_t)((stage * kSlots + s2) * kTileW) * 4u;
            for (int i = tid; i < (kF * kE) / 4; i += kThreads) {
                uint32_t w = (uint32_t)(4 * i) ^ ((((uint32_t)i >> 4) & 7u) << 3);
                asm volatile(
                    "cp.async.cg.shared.global [%0], [%1], 16;\n"
                    :: "r"(dbuf + w * 4u), "l"(src + 4 * (size_t)i) : "memory");
            }
        }
    };

    // ---- Prologue: prefetch first kStages-1 pairs ----
#pragma unroll
    for (int p = 0; p < kStages - 1; ++p) {
        load_pair(p);
        asm volatile("cp.async.commit_group;\n" ::: "memory");
    }

    const int xq   = q << 3;
    const int boff = (q << 6) + g;  // 64*q + g

#pragma unroll 1
    for (int it = 0; it < kIters; ++it) {
        const int jt = it + kStages - 1;
        if (jt < kIters) load_pair(jt);
        asm volatile("cp.async.commit_group;\n" ::: "memory");
        asm volatile("cp.async.wait_group %0;\n" :: "n"(kStages - 1) : "memory");
        __syncthreads();

        const int stage = it % kStages;
        const float* Xb = sm + (stage * kSlots + slot) * kTileW + boff;

        float acc[8][4];
#pragma unroll
        for (int n = 0; n < 8; ++n)
#pragma unroll
            for (int r = 0; r < 4; ++r) acc[n][r] = 0.f;

        // proj[d, e] = sum_f Theta[d,f] * X[f,e]; B frag b0:(k=q, n=g),
        // b1:(k=q+4, n=g). With the swizzle, the address collapses to
        // base + 512k (+256 for b1) + ((8n) ^ 8q (^32)).
#pragma unroll
        for (int k = 0; k < kK; ++k) {
            const float* Xk = Xb + 512 * k;
#pragma unroll
            for (int n = 0; n < 8; ++n) {
                const uint32_t b0 = __float_as_uint(Xk[(8 * n) ^ xq]);
                const uint32_t b1 = __float_as_uint(Xk[256 + ((8 * n) ^ xq ^ 32)]);
                mma8(acc[n], af[k], b0, b1);
            }
        }

        // ---- Epilogue: L_p[b,d] = sum_e proj^2, reduced within each quad.
        // D frag: c0:(g, 8n+2q) c1:(g, 8n+2q+1) c2:(g+8, ...) c3.
        const size_t bcur = bstart + 2 * it + slot;
        float* op = out + bcur * kD + dbase;
        float s0 = 0.f, s1 = 0.f;
#pragma unroll
        for (int n = 0; n < 8; ++n) {
            s0 = fmaf(acc[n][0], acc[n][0], s0);
            s0 = fmaf(acc[n][1], acc[n][1], s0);
            s1 = fmaf(acc[n][2], acc[n][2], s1);
            s1 = fmaf(acc[n][3], acc[n][3], s1);
        }
        s0 += __shfl_xor_sync(0xffffffffu, s0, 1);
        s0 += __shfl_xor_sync(0xffffffffu, s0, 2);
        s1 += __shfl_xor_sync(0xffffffffu, s1, 1);
        s1 += __shfl_xor_sync(0xffffffffu, s1, 2);
        if (q == 0) {
            op[g]     = s0;
            op[g + 8] = s1;
        }
        __syncthreads();
    }
}

extern "C" void kernel_launch(void* const* d_in, const int* in_sizes, int n_in,
                              void* d_out, int out_size) {
    const float* X  = (const float*)d_in[0];   // inputs [16384, 50, 64] fp32
    const float* Th = (const float*)d_in[1];   // Theta  [128, 50] fp32
    float* out      = (float*)d_out;           // [16384, 128] fp32
    (void)in_sizes; (void)n_in; (void)out_size;

    cudaFuncSetAttribute(InnerProduct_tf32_kernel,
                         cudaFuncAttributeMaxDynamicSharedMemorySize, kSmemBytes);
    InnerProduct_tf32_kernel<<<kGrid, kThreads, kSmemBytes>>>(X, Th, out);
}

// round 6
// speedup vs baseline: 1.1951x; 1.1951x over previous
#include <cuda_runtime.h>
#include <cuda_fp16.h>
#include <cstdint>

namespace {
constexpr int kF       = 50;
constexpr int kE       = 64;
constexpr int kD       = 128;
constexpr int kIters   = 8;                  // b's per CTA
constexpr int kGrid    = 16384 / kIters;     // 2048 CTAs
constexpr int kThreads = 256;
constexpr uint32_t kBufB = 8192;             // X tile: 64 e-rows x 128B (64 fp16 f)
}

__device__ __forceinline__ uint32_t smem_u32(const void* p) {
    uint32_t a;
    asm("{ .reg .u64 t; cvta.to.shared.u64 t, %1; cvt.u32.u64 %0, t; }"
        : "=r"(a) : "l"(p));
    return a;
}

__device__ __forceinline__ uint32_t packh2(float lo, float hi) {
    __half2 h = __floats2half2_rn(lo, hi);
    return *reinterpret_cast<uint32_t*>(&h);
}

__device__ __forceinline__ void ldsm4(uint32_t& r0, uint32_t& r1, uint32_t& r2,
                                      uint32_t& r3, uint32_t a) {
    asm volatile("ldmatrix.sync.aligned.m8n8.x4.shared.b16 {%0,%1,%2,%3}, [%4];"
                 : "=r"(r0), "=r"(r1), "=r"(r2), "=r"(r3) : "r"(a));
}

__device__ __forceinline__ void mma16816(float d[4], const uint32_t a[4],
                                         uint32_t b0, uint32_t b1) {
    asm volatile(
        "mma.sync.aligned.m16n8k16.row.col.f32.f16.f16.f32 "
        "{%0,%1,%2,%3}, {%4,%5,%6,%7}, {%8,%9}, {%0,%1,%2,%3};"
        : "+f"(d[0]), "+f"(d[1]), "+f"(d[2]), "+f"(d[3])
        : "r"(a[0]), "r"(a[1]), "r"(a[2]), "r"(a[3]), "r"(b0), "r"(b1));
}

__global__ void __launch_bounds__(kThreads, 2)
InnerProduct_f16_kernel(const float* __restrict__ X,
                        const float* __restrict__ Th,
                        float* __restrict__ out) {
    __shared__ __align__(16) char xs[2 * kBufB];   // 2-stage X double buffer
    __shared__ float scratch[2][2][kD];            // [parity][ehalf][d]

    const int tid  = threadIdx.x;
    const int lane = tid & 31;
    const int warp = tid >> 5;
    const int g    = lane >> 2;       // 0..7
    const int q    = lane & 3;        // 0..3
    const int dbase = (warp & 3) << 5;   // 32 d-rows per warp
    const int ehalf = warp >> 2;         // 0/1: e-range [ehalf*32, +32)

    // ---- Build Theta A-fragments (fp16) in registers, once.
    // m16n8k16 A frag: a0:(row g,      f 16s+2q,+1)  a1:(row g+8,  same f)
    //                  a2:(row g,      f 16s+2q+8,+1) a3:(row g+8, same f)
    // K padded 50 -> 64 with zeros (pad products are exactly 0).
    uint32_t af[2][4][4];
#pragma unroll
    for (int t = 0; t < 2; ++t)
#pragma unroll
        for (int s = 0; s < 4; ++s) {
            const int r0 = dbase + 16 * t + g;
            const int r1 = r0 + 8;
            const int f0 = 16 * s + 2 * q;
            const int f1 = f0 + 8;
            auto thv = [&](int d, int f) -> float {
                return (f < kF) ? Th[d * kF + f] : 0.f;
            };
            af[t][s][0] = packh2(thv(r0, f0), thv(r0, f0 + 1));
            af[t][s][1] = packh2(thv(r1, f0), thv(r1, f0 + 1));
            af[t][s][2] = packh2(thv(r0, f1), thv(r0, f1 + 1));
            af[t][s][3] = packh2(thv(r1, f1), thv(r1, f1 + 1));
        }

    const uint32_t sb = smem_u32(xs);
    const size_t bstart = (size_t)blockIdx.x * kIters;

    // ---- Loader: transpose X[b] ([f=50][e=64] fp32, e-contig) into smem tile
    // [e=64 rows][f=64 fp16] (f-contig, zero-padded), SW128 swizzle.
    // 512 16B-store tasks per tile; 2 tasks/thread. Task = kb*64 + e.
    uint32_t v[2][8];  // staged+converted tiles for 2 b's in flight

    auto ldg_cvt = [&](int b, uint32_t* dst) {
        const float* src = X + (bstart + b) * (size_t)(kF * kE);
#pragma unroll
        for (int i = 0; i < 2; ++i) {
            const int task = tid + kThreads * i;
            const int e  = task & 63;
            const int kb = task >> 6;          // 16B block: f = 8*kb .. +7
            float f[8];
#pragma unroll
            for (int j = 0; j < 8; ++j) {
                const int fj = kb * 8 + j;
                f[j] = (fj < kF) ? src[fj * kE + e] : 0.f;
            }
            dst[i * 4 + 0] = packh2(f[0], f[1]);
            dst[i * 4 + 1] = packh2(f[2], f[3]);
            dst[i * 4 + 2] = packh2(f[4], f[5]);
            dst[i * 4 + 3] = packh2(f[6], f[7]);
        }
    };
    auto sts_tile = [&](int stage, const uint32_t* vv) {
        const uint32_t base = sb + (uint32_t)stage * kBufB;
#pragma unroll
        for (int i = 0; i < 2; ++i) {
            const int task = tid + kThreads * i;
            const uint32_t e  = (uint32_t)(task & 63);
            const uint32_t kb = (uint32_t)(task >> 6);
            const uint32_t off = e * 128u + ((kb ^ (e & 7u)) << 4);
            asm volatile("st.shared.v4.b32 [%0], {%1,%2,%3,%4};"
                         :: "r"(base + off), "r"(vv[i * 4 + 0]), "r"(vv[i * 4 + 1]),
                            "r"(vv[i * 4 + 2]), "r"(vv[i * 4 + 3]) : "memory");
        }
    };

    // ldmatrix lane geometry: m = lane/8 selects {ntile-lo,k-lo | lo,k-hi |
    // hi,k-lo | hi,k-hi}; r = lane%8 is the e-row within the 8x8 matrix.
    const int m   = lane >> 3;
    const int r8  = lane & 7;
    const int klo = m & 1;
    const int eL0 = ehalf * 32 + ((m >> 1) << 3) + r8;  // p=0 base e-row

    // ---- Prologue ----
    ldg_cvt(0, v[0]);
    sts_tile(0, v[0]);
    ldg_cvt(1, v[1]);
    __syncthreads();

#pragma unroll 1
    for (int it = 0; it < kIters; ++it) {
        const uint32_t base = sb + (uint32_t)(it & 1) * kBufB;

        float acc[2][4][4];
#pragma unroll
        for (int t = 0; t < 2; ++t)
#pragma unroll
            for (int n = 0; n < 4; ++n)
#pragma unroll
                for (int c = 0; c < 4; ++c) acc[t][n][c] = 0.f;

        // proj[d,e] = sum_f Theta[d,f] * X[f,e]
#pragma unroll
        for (int s = 0; s < 4; ++s) {
#pragma unroll
            for (int p = 0; p < 2; ++p) {
                const uint32_t e = (uint32_t)(eL0 + 16 * p);
                const uint32_t kb = (uint32_t)(2 * s + klo);
                uint32_t b0, b1, b2, b3;
                ldsm4(b0, b1, b2, b3, base + e * 128u + ((kb ^ (e & 7u)) << 4));
                mma16816(acc[0][2 * p + 0], af[0][s], b0, b1);
                mma16816(acc[1][2 * p + 0], af[1][s], b0, b1);
                mma16816(acc[0][2 * p + 1], af[0][s], b2, b3);
                mma16816(acc[1][2 * p + 1], af[1][s], b2, b3);
            }
        }

        // ---- Epilogue: partial L_p over this warp's 32 e's, quad-reduced.
        // C frag: c0:(g, 2q) c1:(g, 2q+1) c2:(g+8, ..) c3.
        const int par = it & 1;
#pragma unroll
        for (int t = 0; t < 2; ++t) {
            float s0 = 0.f, s1 = 0.f;
#pragma unroll
            for (int n = 0; n < 4; ++n) {
                s0 = fmaf(acc[t][n][0], acc[t][n][0], s0);
                s0 = fmaf(acc[t][n][1], acc[t][n][1], s0);
                s1 = fmaf(acc[t][n][2], acc[t][n][2], s1);
                s1 = fmaf(acc[t][n][3], acc[t][n][3], s1);
            }
            s0 += __shfl_xor_sync(0xffffffffu, s0, 1);
            s0 += __shfl_xor_sync(0xffffffffu, s0, 2);
            s1 += __shfl_xor_sync(0xffffffffu, s1, 1);
            s1 += __shfl_xor_sync(0xffffffffu, s1, 2);
            if (q == 0) {
                scratch[par][ehalf][dbase + 16 * t + g]     = s0;
                scratch[par][ehalf][dbase + 16 * t + g + 8] = s1;
            }
        }

        // ---- Pipeline: store next tile, prefetch tile after next ----
        if (it + 1 < kIters) sts_tile((it + 1) & 1, v[(it + 1) & 1]);
        if (it + 2 < kIters) ldg_cvt(it + 2, v[it & 1]);
        __syncthreads();

        // ---- Combine e-halves and store (coalesced 128 floats per b) ----
        if (tid < kD)
            out[(bstart + it) * kD + tid] =
                scratch[par][0][tid] + scratch[par][1][tid];
    }
}

extern "C" void kernel_launch(void* const* d_in, const int* in_sizes, int n_in,
                              void* d_out, int out_size) {
    const float* X  = (const float*)d_in[0];   // inputs [16384, 50, 64] fp32
    const float* Th = (const float*)d_in[1];   // Theta  [128, 50] fp32
    float* out      = (float*)d_out;           // [16384, 128] fp32
    (void)in_sizes; (void)n_in; (void)out_size;

    InnerProduct_f16_kernel<<<kGrid, kThreads>>>(X, Th, out);
}